// round 11
// baseline (speedup 1.0000x reference)
#include <cuda_runtime.h>
#include <cuda_fp16.h>
#include <cstdint>

// SharedGroupLinearLayer via single-pass fp16 mma.sync, 3 CTAs/SM.
// out = (x·W1^T + b1) + a0 * (x·(W0-W1)^T + (b0-b1)), a0 = sigmoid(x·(rw0-rw1))
// Round 11: TILE_M=32, warp tile 32 tok x 16 out (2 m-tiles x 2 n-tiles:
// one h1 n8-tile + its hd partner) -> acc 16 regs, B 16 regs, ~80 total,
// 3 CTAs/SM (24 warps). Accumulators init with bias; sigmoid in convert.

#define THREADS 256
#define TILE_M  32
#define NTILES  8192
#define GRID    456

#define RAW_PITCH 320     // 256B + 64B pad

// dynamic smem offsets
#define RAW_OFF  0        // 2 x 10240B raw x (32 tok x 320B); init: W fp16 (16KB<20480)
#define AB_OFF   20480    // 4KB fp16 A tile (32 tok x 128B)
#define EMB_OFF  24576    // 16 x 320B
#define RWD_OFF  29696    // 64 f32
#define B1_OFF   29952    // 64 f32
#define BD_OFF   30208    // 64 f32
#define A0_OFF   30464    // 32 f32 gate values (sigmoid applied)
#define SMEM_TOTAL 30720

__device__ __forceinline__ uint32_t smem_u32(const void* p) {
    uint32_t a;
    asm("{ .reg .u64 t; cvta.to.shared.u64 t, %1; cvt.u32.u64 %0, t; }" : "=r"(a) : "l"(p));
    return a;
}
// pack two f32 -> f16x2 word: low 16 = first arg, high = second
__device__ __forceinline__ uint32_t cvt2h(float lo, float hi) {
    uint32_t r;
    asm("cvt.rn.f16x2.f32 %0, %1, %2;" : "=r"(r) : "f"(hi), "f"(lo));
    return r;
}
__device__ __forceinline__ void ldsm_x4(uint32_t* r, uint32_t addr) {
    asm volatile("ldmatrix.sync.aligned.m8n8.x4.shared.b16 {%0,%1,%2,%3}, [%4];"
        : "=r"(r[0]), "=r"(r[1]), "=r"(r[2]), "=r"(r[3]) : "r"(addr));
}
__device__ __forceinline__ void ldsm_x2(uint32_t* r, uint32_t addr) {
    asm volatile("ldmatrix.sync.aligned.m8n8.x2.shared.b16 {%0,%1}, [%2];"
        : "=r"(r[0]), "=r"(r[1]) : "r"(addr));
}
__device__ __forceinline__ void mma_f16(float* d, const uint32_t* a, const uint32_t* b) {
    asm volatile("mma.sync.aligned.m16n8k16.row.col.f32.f16.f16.f32 "
        "{%0,%1,%2,%3}, {%4,%5,%6,%7}, {%8,%9}, {%0,%1,%2,%3};"
        : "+f"(d[0]), "+f"(d[1]), "+f"(d[2]), "+f"(d[3])
        : "r"(a[0]), "r"(a[1]), "r"(a[2]), "r"(a[3]), "r"(b[0]), "r"(b[1]));
}
__device__ __forceinline__ void cp_async16(uint32_t daddr, const void* gptr) {
    asm volatile("cp.async.ca.shared.global [%0], [%1], 16;" :: "r"(daddr), "l"(gptr));
}
#define CP_COMMIT() asm volatile("cp.async.commit_group;" ::: "memory")
#define CP_WAIT1()  asm volatile("cp.async.wait_group 1;" ::: "memory")

__global__ __launch_bounds__(THREADS, 3)
void sgl_fp16b_kernel(const float* __restrict__ x,
                      const float* __restrict__ emb,
                      const float* __restrict__ read_w,
                      const float* __restrict__ w_stack,
                      const float* __restrict__ b_stack,
                      float* __restrict__ out)
{
    extern __shared__ __align__(1024) char smem[];
    const uint32_t sb = smem_u32(smem);

    const int tid  = threadIdx.x;
    const int lane = tid & 31;
    const int wid  = tid >> 5;     // warp w: n-tiles {w, w+8} (h1 + hd partner)

    float* emb_s = (float*)(smem + EMB_OFF);   // 320B pitch (80 floats/row)
    float* rwd_s = (float*)(smem + RWD_OFF);
    float* b1_s  = (float*)(smem + B1_OFF);
    float* bd_s  = (float*)(smem + BD_OFF);
    float* a0_s  = (float*)(smem + A0_OFF);

    // ---- one-time setup ----
    for (int i = tid; i < 64; i += THREADS) {
        rwd_s[i] = read_w[2 * i] - read_w[2 * i + 1];
        float b1 = b_stack[64 + i];
        b1_s[i] = b1;
        bd_s[i] = b_stack[i] - b1;
    }
    for (int i = tid; i < 16 * 64; i += THREADS) {
        int row = i >> 6, k = i & 63;
        emb_s[row * 80 + k] = emb[i];
    }

    // Wcat fp16 staged in RAW area: row n = 128B (64 halves), XOR-swizzled.
    // rows 0-63: W1; rows 64-127: W0-W1. No column permutation (identity).
    for (int i = tid; i < 128 * 32; i += THREADS) {
        int n = i >> 5, kp = (i & 31) * 2;
        int o = n & 63;
        float v0, v1;
        if (n < 64) {
            v0 = w_stack[4096 + o * 64 + kp];
            v1 = w_stack[4096 + o * 64 + kp + 1];
        } else {
            v0 = w_stack[o * 64 + kp]     - w_stack[4096 + o * 64 + kp];
            v1 = w_stack[o * 64 + kp + 1] - w_stack[4096 + o * 64 + kp + 1];
        }
        int off = n * 128 + (((kp >> 3) ^ (n & 7)) << 4) + (kp & 7) * 2;
        *(uint32_t*)(smem + RAW_OFF + off) = cvt2h(v0, v1);
    }
    __syncthreads();

    // ---- B fragments -> registers: nti 0 = h1 tile w, nti 1 = hd tile w+8 ----
    uint32_t B[2][4][2];
    #pragma unroll
    for (int nti = 0; nti < 2; nti++) {
        int row0 = (wid + nti * 8) * 8 + (lane & 7);
        #pragma unroll
        for (int k = 0; k < 4; k++) {
            int unit = k * 2 + ((lane >> 3) & 1);
            ldsm_x2(B[nti][k], sb + RAW_OFF + row0 * 128 + ((unit ^ (row0 & 7)) << 4));
        }
    }
    __syncthreads();   // RAW area now free for x staging

    const int grp = lane >> 2, tc = lane & 3;
    const int o0  = 8 * wid + 2 * tc;
    const float2 b1v = *(const float2*)&b1_s[o0];
    const float2 bdv = *(const float2*)&bd_s[o0];

    const int ct = tid >> 3;         // convert token (0..31)
    const int cp = tid & 7;          // convert part: chunks cp, cp+8

    // ---- prologue: stage first tile's x (32 tok x 256B = 8KB) ----
    {
        const float4* src = (const float4*)x + (size_t)blockIdx.x * (TILE_M * 64 / 4);
        #pragma unroll
        for (int k = 0; k < 2; k++) {
            int j = tid + k * THREADS;
            int t = j >> 4, c = j & 15;
            cp_async16(sb + RAW_OFF + t * RAW_PITCH + c * 16, src + j);
        }
    }
    CP_COMMIT();

    int buf = 0;
    for (int tile = blockIdx.x; tile < NTILES; tile += GRID)
    {
        // prefetch next tile into other raw buffer
        {
            int nt = tile + GRID;
            if (nt < NTILES) {
                const float4* src = (const float4*)x + (size_t)nt * (TILE_M * 64 / 4);
                uint32_t dst = sb + RAW_OFF + (buf ^ 1) * 10240;
                #pragma unroll
                for (int k = 0; k < 2; k++) {
                    int j = tid + k * THREADS;
                    int t = j >> 4, c = j & 15;
                    cp_async16(dst + t * RAW_PITCH + c * 16, src + j);
                }
            }
        }
        CP_COMMIT();
        CP_WAIT1();          // current tile's copy complete
        __syncthreads();     // + separates prev MMA reads from A rewrite

        // ---- convert: 8 threads/token, chunks cp & cp+8, 3-shfl gate ----
        {
            const char* rawb = smem + RAW_OFF + buf * 10240 + ct * RAW_PITCH;
            const float* ep  = &emb_s[(ct & 15) * 80];
            float4 v0 = *(const float4*)(rawb + cp * 16);
            float4 v1 = *(const float4*)(rawb + (cp + 8) * 16);
            float4 e0 = *(const float4*)(ep + cp * 4);
            float4 e1 = *(const float4*)(ep + (cp + 8) * 4);
            v0.x += e0.x; v0.y += e0.y; v0.z += e0.z; v0.w += e0.w;
            v1.x += e1.x; v1.y += e1.y; v1.z += e1.z; v1.w += e1.w;
            const float* r0 = &rwd_s[cp * 4];
            const float* r1 = &rwd_s[(cp + 8) * 4];
            float g = v0.x * r0[0] + v0.y * r0[1] + v0.z * r0[2] + v0.w * r0[3]
                    + v1.x * r1[0] + v1.y * r1[1] + v1.z * r1[2] + v1.w * r1[3];
            g += __shfl_xor_sync(0xffffffffu, g, 1);
            g += __shfl_xor_sync(0xffffffffu, g, 2);
            g += __shfl_xor_sync(0xffffffffu, g, 4);
            if (cp == 0) a0_s[ct] = 1.f / (1.f + __expf(-g));
            uint2 h0 = make_uint2(cvt2h(v0.x, v0.y), cvt2h(v0.z, v0.w));
            uint2 h1 = make_uint2(cvt2h(v1.x, v1.y), cvt2h(v1.z, v1.w));
            uint32_t of0 = (uint32_t)(ct * 128 + (((cp >> 1) ^ (ct & 7)) << 4) + (cp & 1) * 8);
            uint32_t of1 = (uint32_t)(ct * 128 + ((((cp + 8) >> 1) ^ (ct & 7)) << 4) + (cp & 1) * 8);
            *(uint2*)(smem + AB_OFF + of0) = h0;
            *(uint2*)(smem + AB_OFF + of1) = h1;
        }
        __syncthreads();

        // ---- MMA: single fp16 pass; acc initialized with bias ----
        float acc[2][2][4];
        #pragma unroll
        for (int m = 0; m < 2; m++) {
            acc[m][0][0] = b1v.x; acc[m][0][1] = b1v.y;
            acc[m][0][2] = b1v.x; acc[m][0][3] = b1v.y;
            acc[m][1][0] = bdv.x; acc[m][1][1] = bdv.y;
            acc[m][1][2] = bdv.x; acc[m][1][3] = bdv.y;
        }

        #pragma unroll
        for (int k = 0; k < 4; k++) {
            #pragma unroll
            for (int m = 0; m < 2; m++) {
                int tok  = m * 16 + (lane & 15);
                int unit = k * 2 + (lane >> 4);
                uint32_t aaddr = sb + AB_OFF + tok * 128 + ((unit ^ (tok & 7)) << 4);
                uint32_t A[4];
                ldsm_x4(A, aaddr);
                mma_f16(acc[m][0], A, B[0][k]);
                mma_f16(acc[m][1], A, B[1][k]);
            }
        }

        // ---- epilogue: gate combine + STG.64 ----
        {
            float* outb = out + (size_t)tile * (TILE_M * 64);
            #pragma unroll
            for (int m = 0; m < 2; m++) {
                int t0 = m * 16 + grp;
                int t1 = t0 + 8;
                float a00 = a0_s[t0];
                float a01 = a0_s[t1];
                float2 w0, w1;
                w0.x = fmaf(a00, acc[m][1][0], acc[m][0][0]);
                w0.y = fmaf(a00, acc[m][1][1], acc[m][0][1]);
                w1.x = fmaf(a01, acc[m][1][2], acc[m][0][2]);
                w1.y = fmaf(a01, acc[m][1][3], acc[m][0][3]);
                *(float2*)&outb[t0 * 64 + o0] = w0;
                *(float2*)&outb[t1 * 64 + o0] = w1;
            }
        }
        buf ^= 1;
        // next iteration's top __syncthreads separates this MMA/epilogue
        // from the next convert's A-tile rewrite.
    }
}

extern "C" void kernel_launch(void* const* d_in, const int* in_sizes, int n_in,
                              void* d_out, int out_size)
{
    const float* x       = (const float*)d_in[0];
    const float* emb     = (const float*)d_in[1];
    const float* read_w  = (const float*)d_in[2];
    const float* w_stack = (const float*)d_in[3];
    const float* b_stack = (const float*)d_in[4];
    float* out = (float*)d_out;

    cudaFuncSetAttribute(sgl_fp16b_kernel, cudaFuncAttributeMaxDynamicSharedMemorySize, SMEM_TOTAL);
    sgl_fp16b_kernel<<<GRID, THREADS, SMEM_TOTAL>>>(x, emb, read_w, w_stack, b_stack, out);
}

// round 12
// speedup vs baseline: 1.0929x; 1.0929x over previous
#include <cuda_runtime.h>
#include <cuda_fp16.h>
#include <cstdint>

// SharedGroupLinearLayer via single-pass fp16 mma.sync, 3 CTAs/SM target.
// out = (x·W1^T + b1) + a0 * (x·(W0-W1)^T + (b0-b1)), a0 = sigmoid(x·(rw0-rw1))
// Round 12: R10 geometry (TILE_M=64, warp 32tok x 32out, acc32+B32) with
//  - __launch_bounds__(256,3): 85-reg cap -> 24 warps/SM
//  - thread-private raw staging (cp.async own-data): no barrier before convert
//  - ONE barrier per tile; A-tile + gate double-buffered
//  - sigmoid in convert; biases loaded from SMEM in epilogue (no persistent regs)

#define THREADS 256
#define TILE_M  64
#define NTILES  4096
#define GRID    456
#define SLOT    80        // 64B payload + 16B pad: conflict-free LDS.128

// dynamic smem offsets
#define RAW_OFF  0        // 2 x 20480B (256 thr x 80B); init: W fp16 tile (16KB)
#define AB_OFF   40960    // 2 x 8192B fp16 A tile (64 tok x 128B)
#define EMB_OFF  57344    // 16 x 320B
#define RWD_OFF  62464    // 64 f32
#define B1_OFF   62720    // 64 f32
#define BD_OFF   62976    // 64 f32
#define A0_OFF   63232    // 2 x 64 f32 gate (sigmoid applied)
#define SMEM_TOTAL 63744

__device__ __forceinline__ uint32_t smem_u32(const void* p) {
    uint32_t a;
    asm("{ .reg .u64 t; cvta.to.shared.u64 t, %1; cvt.u32.u64 %0, t; }" : "=r"(a) : "l"(p));
    return a;
}
// pack two f32 -> f16x2 word: low 16 = first arg, high = second
__device__ __forceinline__ uint32_t cvt2h(float lo, float hi) {
    uint32_t r;
    asm("cvt.rn.f16x2.f32 %0, %1, %2;" : "=r"(r) : "f"(hi), "f"(lo));
    return r;
}
__device__ __forceinline__ void ldsm_x4(uint32_t* r, uint32_t addr) {
    asm volatile("ldmatrix.sync.aligned.m8n8.x4.shared.b16 {%0,%1,%2,%3}, [%4];"
        : "=r"(r[0]), "=r"(r[1]), "=r"(r[2]), "=r"(r[3]) : "r"(addr));
}
__device__ __forceinline__ void ldsm_x2(uint32_t* r, uint32_t addr) {
    asm volatile("ldmatrix.sync.aligned.m8n8.x2.shared.b16 {%0,%1}, [%2];"
        : "=r"(r[0]), "=r"(r[1]) : "r"(addr));
}
__device__ __forceinline__ void mma_f16(float* d, const uint32_t* a, const uint32_t* b) {
    asm volatile("mma.sync.aligned.m16n8k16.row.col.f32.f16.f16.f32 "
        "{%0,%1,%2,%3}, {%4,%5,%6,%7}, {%8,%9}, {%0,%1,%2,%3};"
        : "+f"(d[0]), "+f"(d[1]), "+f"(d[2]), "+f"(d[3])
        : "r"(a[0]), "r"(a[1]), "r"(a[2]), "r"(a[3]), "r"(b[0]), "r"(b[1]));
}
__device__ __forceinline__ void cp_async16(uint32_t daddr, const void* gptr) {
    asm volatile("cp.async.ca.shared.global [%0], [%1], 16;" :: "r"(daddr), "l"(gptr));
}
#define CP_COMMIT() asm volatile("cp.async.commit_group;" ::: "memory")
#define CP_WAIT0()  asm volatile("cp.async.wait_group 0;" ::: "memory")
#define CP_WAIT1()  asm volatile("cp.async.wait_group 1;" ::: "memory")

__global__ __launch_bounds__(THREADS, 3)
void sgl_fp16c_kernel(const float* __restrict__ x,
                      const float* __restrict__ emb,
                      const float* __restrict__ read_w,
                      const float* __restrict__ w_stack,
                      const float* __restrict__ b_stack,
                      float* __restrict__ out)
{
    extern __shared__ __align__(1024) char smem[];
    const uint32_t sb = smem_u32(smem);

    const int tid  = threadIdx.x;
    const int lane = tid & 31;
    const int wid  = tid >> 5;
    const int q    = wid & 3;      // n-column group
    const int r    = wid >> 2;     // m-half (tokens r*32..r*32+31)

    float* emb_s = (float*)(smem + EMB_OFF);   // 320B pitch
    float* rwd_s = (float*)(smem + RWD_OFF);

    // ---- one-time setup ----
    for (int i = tid; i < 64; i += THREADS) {
        rwd_s[i] = read_w[2 * i] - read_w[2 * i + 1];
        float b1 = b_stack[64 + i];
        ((float*)(smem + B1_OFF))[i] = b1;
        ((float*)(smem + BD_OFF))[i] = b_stack[i] - b1;
    }
    for (int i = tid; i < 16 * 64; i += THREADS) {
        int row = i >> 6, k = i & 63;
        emb_s[row * 80 + k] = emb[i];
    }

    // Wcat fp16 staged in RAW area, column-permuted so thread (q,tc) owns
    // 4 contiguous outputs 16q+4tc..+3. Row n = 128B, XOR-swizzled 16B units.
    for (int i = tid; i < 128 * 32; i += THREADS) {
        int n = i >> 5, kp = (i & 31) * 2;
        int half = n >> 6;              // 0: W1, 1: W0-W1
        int nn = n & 63;
        int p = nn & 7, t = (nn >> 3) & 1;
        int o = (nn & 48) + ((p >> 1) << 2) + 2 * t + (p & 1);
        float v0, v1;
        if (half == 0) {
            v0 = w_stack[4096 + o * 64 + kp];
            v1 = w_stack[4096 + o * 64 + kp + 1];
        } else {
            v0 = w_stack[o * 64 + kp]     - w_stack[4096 + o * 64 + kp];
            v1 = w_stack[o * 64 + kp + 1] - w_stack[4096 + o * 64 + kp + 1];
        }
        int off = n * 128 + (((kp >> 3) ^ (n & 7)) << 4) + (kp & 7) * 2;
        *(uint32_t*)(smem + RAW_OFF + off) = cvt2h(v0, v1);
    }
    __syncthreads();

    // ---- B fragments -> registers (kept for whole kernel) ----
    uint32_t B[4][4][2];
    #pragma unroll
    for (int nti = 0; nti < 4; nti++) {
        int nt = 2 * q + (nti & 1) + ((nti >> 1) << 3);
        #pragma unroll
        for (int k = 0; k < 4; k++) {
            int row  = nt * 8 + (lane & 7);
            int unit = k * 2 + ((lane >> 3) & 1);
            ldsm_x2(B[nti][k], sb + RAW_OFF + row * 128 + ((unit ^ (row & 7)) << 4));
        }
    }
    __syncthreads();   // RAW area now free for x staging

    const int grp = lane >> 2, tc = lane & 3;
    const int o0  = 16 * q + 4 * tc;
    const int ct  = tid >> 2;        // convert token (0..63)
    const int cp  = tid & 3;         // convert part: chunks cp + 4i

    // gmem float4 base for this thread's private chunks
    const float4* xth = (const float4*)x + (ct << 4) + cp;

    // ---- prologue: stage tile0, convert tile0 -> A[0], stage tile1 ----
    {
        const float4* src = xth + (size_t)blockIdx.x * 1024;
        uint32_t dst = sb + RAW_OFF + tid * SLOT;
        #pragma unroll
        for (int i = 0; i < 4; i++) cp_async16(dst + i * 16, src + 4 * i);
    }
    CP_COMMIT();
    CP_WAIT0();
    {   // convert tile0 (raw[0] -> A[0], a0[0])
        float g = 0.f;
        #pragma unroll
        for (int i = 0; i < 4; i++) {
            int c = cp + 4 * i;
            float4 v = *(const float4*)(smem + RAW_OFF + tid * SLOT + i * 16);
            float4 e = *(const float4*)(&emb_s[(ct & 15) * 80 + c * 4]);
            v.x += e.x; v.y += e.y; v.z += e.z; v.w += e.w;
            const float* rp = &rwd_s[c * 4];
            g += v.x * rp[0] + v.y * rp[1] + v.z * rp[2] + v.w * rp[3];
            uint2 h = make_uint2(cvt2h(v.x, v.y), cvt2h(v.z, v.w));
            uint32_t off = (uint32_t)(ct * 128 + (((c >> 1) ^ (ct & 7)) << 4) + (c & 1) * 8);
            *(uint2*)(smem + AB_OFF + off) = h;
        }
        g += __shfl_xor_sync(0xffffffffu, g, 1);
        g += __shfl_xor_sync(0xffffffffu, g, 2);
        if (cp == 0) ((float*)(smem + A0_OFF))[ct] = 1.f / (1.f + __expf(-g));
    }
    {   // stage tile1 -> raw[1]
        int nt = blockIdx.x + GRID;
        if (nt < NTILES) {
            const float4* src = xth + (size_t)nt * 1024;
            uint32_t dst = sb + RAW_OFF + 20480 + tid * SLOT;
            #pragma unroll
            for (int i = 0; i < 4; i++) cp_async16(dst + i * 16, src + 4 * i);
        }
    }
    CP_COMMIT();

    int b = 0;
    for (int tile = blockIdx.x; tile < NTILES; tile += GRID)
    {
        __syncthreads();   // A[b]/a0[b] visible; all reads of A[b^1] done

        // stage tile+2 into raw[b] (its data was converted last iteration,
        // and each raw slot is thread-private: no cross-thread hazard)
        {
            int pf = tile + 2 * GRID;
            if (pf < NTILES) {
                const float4* src = xth + (size_t)pf * 1024;
                uint32_t dst = sb + RAW_OFF + b * 20480 + tid * SLOT;
                #pragma unroll
                for (int i = 0; i < 4; i++) cp_async16(dst + i * 16, src + 4 * i);
            }
        }
        CP_COMMIT();
        CP_WAIT1();        // raw[b^1] (tile+1, own data) complete

        // ---- convert tile+1 -> A[b^1] (no barrier needed: own raw data;
        //      WAR on A[b^1] protected by the sync above) ----
        if (tile + GRID < NTILES) {
            float g = 0.f;
            #pragma unroll
            for (int i = 0; i < 4; i++) {
                int c = cp + 4 * i;
                float4 v = *(const float4*)(smem + RAW_OFF + (b ^ 1) * 20480 + tid * SLOT + i * 16);
                float4 e = *(const float4*)(&emb_s[(ct & 15) * 80 + c * 4]);
                v.x += e.x; v.y += e.y; v.z += e.z; v.w += e.w;
                const float* rp = &rwd_s[c * 4];
                g += v.x * rp[0] + v.y * rp[1] + v.z * rp[2] + v.w * rp[3];
                uint2 h = make_uint2(cvt2h(v.x, v.y), cvt2h(v.z, v.w));
                uint32_t off = (uint32_t)(ct * 128 + (((c >> 1) ^ (ct & 7)) << 4) + (c & 1) * 8);
                *(uint2*)(smem + AB_OFF + (b ^ 1) * 8192 + off) = h;
            }
            g += __shfl_xor_sync(0xffffffffu, g, 1);
            g += __shfl_xor_sync(0xffffffffu, g, 2);
            if (cp == 0) ((float*)(smem + A0_OFF))[(b ^ 1) * 64 + ct] = 1.f / (1.f + __expf(-g));
        }

        // ---- MMA tile (A[b]): single fp16 pass, B in registers ----
        float acc[2][4][4];
        #pragma unroll
        for (int m = 0; m < 2; m++)
            #pragma unroll
            for (int n = 0; n < 4; n++) {
                acc[m][n][0] = 0.f; acc[m][n][1] = 0.f;
                acc[m][n][2] = 0.f; acc[m][n][3] = 0.f;
            }

        #pragma unroll
        for (int k = 0; k < 4; k++) {
            #pragma unroll
            for (int m = 0; m < 2; m++) {
                int tok  = r * 32 + m * 16 + (lane & 15);
                int unit = k * 2 + (lane >> 4);
                uint32_t aaddr = sb + AB_OFF + b * 8192 + tok * 128 + ((unit ^ (tok & 7)) << 4);
                uint32_t A[4];
                ldsm_x4(A, aaddr);
                mma_f16(acc[m][0], A, B[0][k]);
                mma_f16(acc[m][1], A, B[1][k]);
                mma_f16(acc[m][2], A, B[2][k]);
                mma_f16(acc[m][3], A, B[3][k]);
            }
        }

        // ---- epilogue: gate combine + bias + STG.128 ----
        {
            float* outb = out + (size_t)tile * (TILE_M * 64);
            const float* a0r = (const float*)(smem + A0_OFF) + b * 64;
            float4 b1v = *(const float4*)(smem + B1_OFF + o0 * 4);
            float4 bdv = *(const float4*)(smem + BD_OFF + o0 * 4);
            #pragma unroll
            for (int m = 0; m < 2; m++) {
                int t0 = r * 32 + m * 16 + grp;
                int t1 = t0 + 8;
                float a00 = a0r[t0];
                float a01 = a0r[t1];
                float4 w;
                w.x = fmaf(a00, acc[m][2][0] + bdv.x, acc[m][0][0] + b1v.x);
                w.y = fmaf(a00, acc[m][2][1] + bdv.y, acc[m][0][1] + b1v.y);
                w.z = fmaf(a00, acc[m][3][0] + bdv.z, acc[m][1][0] + b1v.z);
                w.w = fmaf(a00, acc[m][3][1] + bdv.w, acc[m][1][1] + b1v.w);
                *(float4*)&outb[t0 * 64 + o0] = w;
                w.x = fmaf(a01, acc[m][2][2] + bdv.x, acc[m][0][2] + b1v.x);
                w.y = fmaf(a01, acc[m][2][3] + bdv.y, acc[m][0][3] + b1v.y);
                w.z = fmaf(a01, acc[m][3][2] + bdv.z, acc[m][1][2] + b1v.z);
                w.w = fmaf(a01, acc[m][3][3] + bdv.w, acc[m][1][3] + b1v.w);
                *(float4*)&outb[t1 * 64 + o0] = w;
            }
        }
        b ^= 1;
    }
}

extern "C" void kernel_launch(void* const* d_in, const int* in_sizes, int n_in,
                              void* d_out, int out_size)
{
    const float* x       = (const float*)d_in[0];
    const float* emb     = (const float*)d_in[1];
    const float* read_w  = (const float*)d_in[2];
    const float* w_stack = (const float*)d_in[3];
    const float* b_stack = (const float*)d_in[4];
    float* out = (float*)d_out;

    cudaFuncSetAttribute(sgl_fp16c_kernel, cudaFuncAttributeMaxDynamicSharedMemorySize, SMEM_TOTAL);
    sgl_fp16c_kernel<<<GRID, THREADS, SMEM_TOTAL>>>(x, emb, read_w, w_stack, b_stack, out);
}

// round 13
// speedup vs baseline: 1.1100x; 1.0156x over previous
#include <cuda_runtime.h>
#include <cuda_fp16.h>
#include <cstdint>

// SharedGroupLinearLayer via single-pass fp16 mma.sync, 2 CTAs/SM.
// out = (x·W1^T + b1) + a0 * (x·(W0-W1)^T + (b0-b1)), a0 = sigmoid(x·(rw0-rw1))
// Round 13: x flows through REGISTERS (no raw SMEM staging, no cp.async).
// Per iteration: LDG x(i+1) into 16 regs -> MMA(i) (hides LDG latency) ->
// convert regs -> A[b^1] -> epilogue(i). One barrier per tile. A + gate
// double buffered. TILE_M=64, warp 32tok x 32out, B fragments in registers.

#define THREADS 256
#define TILE_M  64
#define NTILES  4096
#define GRID    304

// dynamic smem offsets
#define AB_OFF   0        // 2 x 8192B fp16 A tile; init: W fp16 tile (16KB)
#define EMB_OFF  16384    // 16 x 320B
#define RWD_OFF  21504    // 64 f32
#define B1_OFF   21760    // 64 f32
#define BD_OFF   22016    // 64 f32
#define A0_OFF   22272    // 2 x 64 f32 gate (sigmoid applied)
#define SMEM_TOTAL 22784

__device__ __forceinline__ uint32_t smem_u32(const void* p) {
    uint32_t a;
    asm("{ .reg .u64 t; cvta.to.shared.u64 t, %1; cvt.u32.u64 %0, t; }" : "=r"(a) : "l"(p));
    return a;
}
// pack two f32 -> f16x2 word: low 16 = first arg, high = second
__device__ __forceinline__ uint32_t cvt2h(float lo, float hi) {
    uint32_t r;
    asm("cvt.rn.f16x2.f32 %0, %1, %2;" : "=r"(r) : "f"(hi), "f"(lo));
    return r;
}
__device__ __forceinline__ void ldsm_x4(uint32_t* r, uint32_t addr) {
    asm volatile("ldmatrix.sync.aligned.m8n8.x4.shared.b16 {%0,%1,%2,%3}, [%4];"
        : "=r"(r[0]), "=r"(r[1]), "=r"(r[2]), "=r"(r[3]) : "r"(addr));
}
__device__ __forceinline__ void ldsm_x2(uint32_t* r, uint32_t addr) {
    asm volatile("ldmatrix.sync.aligned.m8n8.x2.shared.b16 {%0,%1}, [%2];"
        : "=r"(r[0]), "=r"(r[1]) : "r"(addr));
}
__device__ __forceinline__ void mma_f16(float* d, const uint32_t* a, const uint32_t* b) {
    asm volatile("mma.sync.aligned.m16n8k16.row.col.f32.f16.f16.f32 "
        "{%0,%1,%2,%3}, {%4,%5,%6,%7}, {%8,%9}, {%0,%1,%2,%3};"
        : "+f"(d[0]), "+f"(d[1]), "+f"(d[2]), "+f"(d[3])
        : "r"(a[0]), "r"(a[1]), "r"(a[2]), "r"(a[3]), "r"(b[0]), "r"(b[1]));
}

__global__ __launch_bounds__(THREADS, 2)
void sgl_fp16d_kernel(const float* __restrict__ x,
                      const float* __restrict__ emb,
                      const float* __restrict__ read_w,
                      const float* __restrict__ w_stack,
                      const float* __restrict__ b_stack,
                      float* __restrict__ out)
{
    extern __shared__ __align__(1024) char smem[];
    const uint32_t sb = smem_u32(smem);

    const int tid  = threadIdx.x;
    const int lane = tid & 31;
    const int wid  = tid >> 5;
    const int q    = wid & 3;      // n-column group
    const int r    = wid >> 2;     // m-half (tokens r*32..r*32+31)

    float* emb_s = (float*)(smem + EMB_OFF);   // 320B pitch
    float* rwd_s = (float*)(smem + RWD_OFF);

    // ---- one-time setup ----
    for (int i = tid; i < 64; i += THREADS) {
        rwd_s[i] = read_w[2 * i] - read_w[2 * i + 1];
        float b1 = b_stack[64 + i];
        ((float*)(smem + B1_OFF))[i] = b1;
        ((float*)(smem + BD_OFF))[i] = b_stack[i] - b1;
    }
    for (int i = tid; i < 16 * 64; i += THREADS) {
        int row = i >> 6, k = i & 63;
        emb_s[row * 80 + k] = emb[i];
    }

    // Wcat fp16 staged in AB area (16KB exactly), column-permuted so thread
    // (q,tc) owns 4 contiguous outputs 16q+4tc..+3. Row n = 128B, XOR-swizzled.
    for (int i = tid; i < 128 * 32; i += THREADS) {
        int n = i >> 5, kp = (i & 31) * 2;
        int half = n >> 6;              // 0: W1, 1: W0-W1
        int nn = n & 63;
        int p = nn & 7, t = (nn >> 3) & 1;
        int o = (nn & 48) + ((p >> 1) << 2) + 2 * t + (p & 1);
        float v0, v1;
        if (half == 0) {
            v0 = w_stack[4096 + o * 64 + kp];
            v1 = w_stack[4096 + o * 64 + kp + 1];
        } else {
            v0 = w_stack[o * 64 + kp]     - w_stack[4096 + o * 64 + kp];
            v1 = w_stack[o * 64 + kp + 1] - w_stack[4096 + o * 64 + kp + 1];
        }
        int off = n * 128 + (((kp >> 3) ^ (n & 7)) << 4) + (kp & 7) * 2;
        *(uint32_t*)(smem + AB_OFF + off) = cvt2h(v0, v1);
    }
    __syncthreads();

    // ---- B fragments -> registers (kept for whole kernel) ----
    uint32_t B[4][4][2];
    #pragma unroll
    for (int nti = 0; nti < 4; nti++) {
        int nt = 2 * q + (nti & 1) + ((nti >> 1) << 3);
        #pragma unroll
        for (int k = 0; k < 4; k++) {
            int row  = nt * 8 + (lane & 7);
            int unit = k * 2 + ((lane >> 3) & 1);
            ldsm_x2(B[nti][k], sb + AB_OFF + row * 128 + ((unit ^ (row & 7)) << 4));
        }
    }
    __syncthreads();   // AB area now free for A tiles

    const int grp = lane >> 2, tc = lane & 3;
    const int o0  = 16 * q + 4 * tc;
    const int ct  = tid >> 2;        // convert token (0..63)
    const int cp  = tid & 3;         // convert part: chunks cp + 4i

    // gmem float4 base for this thread's private chunks (tile stride 1024 f4)
    const float4* xth = (const float4*)x + (ct << 4) + cp;
    const float*  epb = &emb_s[(ct & 15) * 80];
    float* a0b = (float*)(smem + A0_OFF);

    // ---- prologue: convert tile0 -> A[0], a0[0] ----
    {
        const float4* src = xth + (size_t)blockIdx.x * 1024;
        float g = 0.f;
        #pragma unroll
        for (int i = 0; i < 4; i++) {
            int c = cp + 4 * i;
            float4 v = src[4 * i];
            float4 e = *(const float4*)(epb + c * 4);
            v.x += e.x; v.y += e.y; v.z += e.z; v.w += e.w;
            const float* rp = &rwd_s[c * 4];
            g += v.x * rp[0] + v.y * rp[1] + v.z * rp[2] + v.w * rp[3];
            uint2 h = make_uint2(cvt2h(v.x, v.y), cvt2h(v.z, v.w));
            uint32_t off = (uint32_t)(ct * 128 + (((c >> 1) ^ (ct & 7)) << 4) + (c & 1) * 8);
            *(uint2*)(smem + AB_OFF + off) = h;
        }
        g += __shfl_xor_sync(0xffffffffu, g, 1);
        g += __shfl_xor_sync(0xffffffffu, g, 2);
        if (cp == 0) a0b[ct] = 1.f / (1.f + __expf(-g));
    }

    int b = 0;
    for (int tile = blockIdx.x; tile < NTILES; tile += GRID)
    {
        __syncthreads();   // A[b]/a0[b] visible; all MMA reads of A[b^1] done

        const bool hasnext = (tile + GRID) < NTILES;

        // ---- issue LDGs for tile+1 (latency hidden under MMA below) ----
        float4 xv0, xv1, xv2, xv3;
        if (hasnext) {
            const float4* src = xth + (size_t)(tile + GRID) * 1024;
            xv0 = src[0];
            xv1 = src[4];
            xv2 = src[8];
            xv3 = src[12];
        }

        // ---- MMA tile (A[b]): single fp16 pass, B in registers ----
        float acc[2][4][4];
        #pragma unroll
        for (int m = 0; m < 2; m++)
            #pragma unroll
            for (int n = 0; n < 4; n++) {
                acc[m][n][0] = 0.f; acc[m][n][1] = 0.f;
                acc[m][n][2] = 0.f; acc[m][n][3] = 0.f;
            }

        #pragma unroll
        for (int k = 0; k < 4; k++) {
            #pragma unroll
            for (int m = 0; m < 2; m++) {
                int tok  = r * 32 + m * 16 + (lane & 15);
                int unit = k * 2 + (lane >> 4);
                uint32_t aaddr = sb + AB_OFF + b * 8192 + tok * 128 + ((unit ^ (tok & 7)) << 4);
                uint32_t A[4];
                ldsm_x4(A, aaddr);
                mma_f16(acc[m][0], A, B[0][k]);
                mma_f16(acc[m][1], A, B[1][k]);
                mma_f16(acc[m][2], A, B[2][k]);
                mma_f16(acc[m][3], A, B[3][k]);
            }
        }

        // ---- convert tile+1 (register x) -> A[b^1], a0[b^1] ----
        if (hasnext) {
            float g = 0.f;
            float4 vv[4] = { xv0, xv1, xv2, xv3 };
            #pragma unroll
            for (int i = 0; i < 4; i++) {
                int c = cp + 4 * i;
                float4 v = vv[i];
                float4 e = *(const float4*)(epb + c * 4);
                v.x += e.x; v.y += e.y; v.z += e.z; v.w += e.w;
                const float* rp = &rwd_s[c * 4];
                g += v.x * rp[0] + v.y * rp[1] + v.z * rp[2] + v.w * rp[3];
                uint2 h = make_uint2(cvt2h(v.x, v.y), cvt2h(v.z, v.w));
                uint32_t off = (uint32_t)(ct * 128 + (((c >> 1) ^ (ct & 7)) << 4) + (c & 1) * 8);
                *(uint2*)(smem + AB_OFF + (b ^ 1) * 8192 + off) = h;
            }
            g += __shfl_xor_sync(0xffffffffu, g, 1);
            g += __shfl_xor_sync(0xffffffffu, g, 2);
            if (cp == 0) a0b[(b ^ 1) * 64 + ct] = 1.f / (1.f + __expf(-g));
        }

        // ---- epilogue: gate combine + bias + STG.128 ----
        {
            float* outb = out + (size_t)tile * (TILE_M * 64);
            const float* a0r = a0b + b * 64;
            float4 b1v = *(const float4*)(smem + B1_OFF + o0 * 4);
            float4 bdv = *(const float4*)(smem + BD_OFF + o0 * 4);
            #pragma unroll
            for (int m = 0; m < 2; m++) {
                int t0 = r * 32 + m * 16 + grp;
                int t1 = t0 + 8;
                float a00 = a0r[t0];
                float a01 = a0r[t1];
                float4 w;
                w.x = fmaf(a00, acc[m][2][0] + bdv.x, acc[m][0][0] + b1v.x);
                w.y = fmaf(a00, acc[m][2][1] + bdv.y, acc[m][0][1] + b1v.y);
                w.z = fmaf(a00, acc[m][3][0] + bdv.z, acc[m][1][0] + b1v.z);
                w.w = fmaf(a00, acc[m][3][1] + bdv.w, acc[m][1][1] + b1v.w);
                *(float4*)&outb[t0 * 64 + o0] = w;
                w.x = fmaf(a01, acc[m][2][2] + bdv.x, acc[m][0][2] + b1v.x);
                w.y = fmaf(a01, acc[m][2][3] + bdv.y, acc[m][0][3] + b1v.y);
                w.z = fmaf(a01, acc[m][3][2] + bdv.z, acc[m][1][2] + b1v.z);
                w.w = fmaf(a01, acc[m][3][3] + bdv.w, acc[m][1][3] + b1v.w);
                *(float4*)&outb[t1 * 64 + o0] = w;
            }
        }
        b ^= 1;
    }
}

extern "C" void kernel_launch(void* const* d_in, const int* in_sizes, int n_in,
                              void* d_out, int out_size)
{
    const float* x       = (const float*)d_in[0];
    const float* emb     = (const float*)d_in[1];
    const float* read_w  = (const float*)d_in[2];
    const float* w_stack = (const float*)d_in[3];
    const float* b_stack = (const float*)d_in[4];
    float* out = (float*)d_out;

    cudaFuncSetAttribute(sgl_fp16d_kernel, cudaFuncAttributeMaxDynamicSharedMemorySize, SMEM_TOTAL);
    sgl_fp16d_kernel<<<GRID, THREADS, SMEM_TOTAL>>>(x, emb, read_w, w_stack, b_stack, out);
}